// round 16
// baseline (speedup 1.0000x reference)
#include <cuda_runtime.h>
#include <math_constants.h>
#include <cstdint>

#define N_NODES 1024
#define N_EDGES 32768
#define FLATD   4096   // 4*N

// -------- scratch (device globals; zero-initialized at module load) --------
// Zero-state invariant on entry to each call: g_agg==0, g_logits==0, g_v1==0,
// g_count==0, g_done==0, g_done2==0, g_prep_done==0, g_edge_done==0,
// g_vcount==0. g_sumexp zeroed by prep each call. The last value1 block
// restores everything at the end of the call.
__device__ float  g_agg[FLATD];         // aggregated EdgeConv output [n*4 + c]
__device__ float  g_logits[N_EDGES];    // policy logits (accumulated, no bias)
__device__ float  g_v1[64];             // value layer-1 partials (no bias)
__device__ float  g_sumexp;             // softmax denominator
__device__ int    g_count[32];          // per-column-block completion counters
__device__ int    g_done;               // col-blocks whose sum is published
__device__ int    g_done2;              // col-finishers that consumed g_sumexp
__device__ int    g_prep_done;          // prep sub-phase blocks completed
__device__ int    g_edge_done;          // edge sub-phase blocks completed
__device__ int    g_vcount;             // value1 blocks completed
__device__ float  g_tA[N_NODES * 12];   // b1 + [t>=0](w1[t]-w1[N+t]), 12-padded
__device__ float  g_tB[N_NODES * 12];   // [t>=0] w1[N+t], 12-padded

#define PREP_BLOCKS  48               // GEMV blocks 0..47 also run prep
#define EDGE_END     176              // GEMV blocks 48..175 also run edges
#define EDGE_BLOCKS  (EDGE_END - PREP_BLOCKS)   // 128
#define ROWS_PER_BLK 128              // FLATD / 32 row-slices
#define COLS_PER_BLK 1024             // 256 threads * 4 cols (float4)
#define GEMV_BLOCKS  1024             // 32 col-blocks * 32 row-slices
#define V1_BLOCKS    16
#define V1_BASE      GEMV_BLOCKS                          // 1024
#define TOTAL_BLOCKS (V1_BASE + V1_BLOCKS)                // 1040 (single wave)
#define N_PIN        24               // rows/block kept L2-resident (96 MB total)

// evict_last via cache-hint policy (the form ptxas accepts for v4.f32):
// lines survive the streaming flood AND graph-replay boundaries (L2 persists
// across launches; only L1 is flushed per launch).
__device__ __forceinline__ uint64_t make_evict_last_policy() {
    uint64_t pol;
    asm volatile("createpolicy.fractional.L2::evict_last.b64 %0, 1.0;"
                 : "=l"(pol));
    return pol;
}
__device__ __forceinline__ float4 ld_evict_last(const float4* p, uint64_t pol) {
    float4 w;
    asm volatile("ld.global.L2::cache_hint.v4.f32 {%0,%1,%2,%3}, [%4], %5;"
                 : "=f"(w.x), "=f"(w.y), "=f"(w.z), "=f"(w.w)
                 : "l"(p), "l"(pol));
    return w;
}

// == single mega-kernel; prep/edge phases run INSIDE their GEMV blocks ======
__global__ __launch_bounds__(256) void mega_kernel(
        const int* __restrict__ tgt,  const int* __restrict__ eidx,
        const float* __restrict__ w1, const float* __restrict__ b1,
        const float* __restrict__ w2, const float* __restrict__ b2,
        const float* __restrict__ wp, const float* __restrict__ wv1,
        const float* __restrict__ bp,
        const float* __restrict__ bv1,
        const float* __restrict__ wv2, const float* __restrict__ bv2,
        const float* __restrict__ wv3, const float* __restrict__ bv3,
        const float* __restrict__ wv4, const float* __restrict__ bv4,
        float* __restrict__ out) {
    int b = blockIdx.x;
    int t = threadIdx.x;

    if (b < V1_BASE) {
        // ======================= GEMV block (all 1024) =====================
        __shared__ float sx[ROWS_PER_BLK];
        __shared__ int   s_last;
        __shared__ float s_inv;
        int bx = b & 31;           // col block
        int by = b >> 5;           // row slice
        int col  = bx * COLS_PER_BLK + t * 4;
        int row0 = by * ROWS_PER_BLK;

        const float4* wptr = reinterpret_cast<const float4*>(
            wp + (size_t)row0 * N_EDGES + col);
        const size_t stride4 = N_EDGES / 4;

        // ---- phase prelude: prep | edge | prefetch-only ----
        if (b < PREP_BLOCKS) {
            // per-node collapsed first-layer rows; one elem per thread
            int idx = b * 256 + t;           // 12288 elems over 48 blocks
            if (idx == 0) g_sumexp = 0.0f;
            if (idx < N_NODES * 12) {
                int n = idx / 12;
                int k = idx - n * 12;
                float a = 0.0f, bb = 0.0f;
                if (k < 10) {
                    int tn = tgt[n];
                    a = b1[k];
                    if (tn >= 0) {
                        float top = w1[tn * 10 + k];
                        float bot = w1[(N_NODES + tn) * 10 + k];
                        a += top - bot;
                        bb = bot;
                    }
                }
                g_tA[idx] = a;
                g_tB[idx] = bb;
            }
            __threadfence();
            __syncthreads();
            if (t == 0) atomicAdd(&g_prep_done, 1);
#pragma unroll
            for (int i = 0; i < N_PIN; i++)
                asm volatile("prefetch.global.L2 [%0];" ::
                             "l"(wptr + (size_t)i * stride4));
        } else if (b < EDGE_END) {
            // EdgeConv for 256 edges; prefetch first (independent of prep)
            int e = (b - PREP_BLOCKS) * 256 + t;
            int s = eidx[e];            // source
            int d = eidx[N_EDGES + e];  // dest / aggregation node
#pragma unroll
            for (int i = 0; i < N_PIN; i++)
                asm volatile("prefetch.global.L2 [%0];" ::
                             "l"(wptr + (size_t)i * stride4));
            if (t == 0) {
                while (*(volatile int*)&g_prep_done != PREP_BLOCKS) __nanosleep(16);
            }
            __syncthreads();
            __threadfence();

            const float4* tA4 = reinterpret_cast<const float4*>(g_tA) + d * 3;
            const float4* tB4 = reinterpret_cast<const float4*>(g_tB) + s * 3;
            float4 a0 = tA4[0], a1 = tA4[1], a2 = tA4[2];
            float4 c0 = tB4[0], c1 = tB4[1], c2 = tB4[2];

            float h[10];
            h[0] = fmaxf(a0.x + c0.x, 0.f);
            h[1] = fmaxf(a0.y + c0.y, 0.f);
            h[2] = fmaxf(a0.z + c0.z, 0.f);
            h[3] = fmaxf(a0.w + c0.w, 0.f);
            h[4] = fmaxf(a1.x + c1.x, 0.f);
            h[5] = fmaxf(a1.y + c1.y, 0.f);
            h[6] = fmaxf(a1.z + c1.z, 0.f);
            h[7] = fmaxf(a1.w + c1.w, 0.f);
            h[8] = fmaxf(a2.x + c2.x, 0.f);
            h[9] = fmaxf(a2.y + c2.y, 0.f);

            float m[4];
#pragma unroll
            for (int c = 0; c < 4; c++) {
                float acc = b2[c];
#pragma unroll
                for (int k = 0; k < 10; k++) acc += h[k] * w2[k * 4 + c];
                m[c] = acc;
            }
            float mx = fmaxf(fmaxf(m[0], m[1]), fmaxf(m[2], m[3]));
            float sum = 0.0f;
#pragma unroll
            for (int c = 0; c < 4; c++) { m[c] = __expf(m[c] - mx); sum += m[c]; }
            float inv = 1.0f / sum;
#pragma unroll
            for (int c = 0; c < 4; c++)
                atomicAdd(&g_agg[d * 4 + c], m[c] * inv);

            __threadfence();
            __syncthreads();
            if (t == 0) atomicAdd(&g_edge_done, 1);
        } else {
            // pure GEMV block: prefetch while prep+edge run
#pragma unroll
            for (int i = 0; i < N_PIN; i++)
                asm volatile("prefetch.global.L2 [%0];" ::
                             "l"(wptr + (size_t)i * stride4));
        }

        // ---- wait for the aggregation to be complete ----
        if (t == 0) {
            while (*(volatile int*)&g_edge_done != EDGE_BLOCKS) __nanosleep(16);
        }
        __syncthreads();
        __threadfence();

        if (t < ROWS_PER_BLK) sx[t] = g_agg[row0 + t];
        __syncthreads();

        uint64_t pol = make_evict_last_policy();
        float4 acc = make_float4(0.f, 0.f, 0.f, 0.f);
        // pinned rows: evict_last -> stay L2-resident across graph replays
#pragma unroll 4
        for (int i = 0; i < N_PIN; i++) {
            float  xv = sx[i];
            float4 w  = ld_evict_last(wptr + (size_t)i * stride4, pol);
            acc.x += xv * w.x;
            acc.y += xv * w.y;
            acc.z += xv * w.z;
            acc.w += xv * w.w;
        }
        // streaming rows: evict_first, never pollute the pinned set
#pragma unroll 8
        for (int i = N_PIN; i < ROWS_PER_BLK; i++) {
            float  xv = sx[i];
            float4 w  = __ldcs(wptr + (size_t)i * stride4);
            acc.x += xv * w.x;
            acc.y += xv * w.y;
            acc.z += xv * w.z;
            acc.w += xv * w.w;
        }
        atomicAdd(&g_logits[col + 0], acc.x);
        atomicAdd(&g_logits[col + 1], acc.y);
        atomicAdd(&g_logits[col + 2], acc.z);
        atomicAdd(&g_logits[col + 3], acc.w);

        // publish atomics (fence), all threads fenced (barrier), count in.
        __threadfence();
        __syncthreads();
        if (t == 0) {
            int old = atomicAdd(&g_count[bx], 1);
            s_last = (old == 31);
        }
        __syncthreads();

        if (s_last) {
            // exp epilogue; no max-subtraction (|logit| << 88, exact softmax).
            float ex[4];
            float lsum = 0.0f;
#pragma unroll
            for (int q = 0; q < 4; q++) {
                int idx = col + q;
                float x = __ldcg(&g_logits[idx]) + __ldg(&bp[idx]);
                ex[q] = __expf(x);
                lsum += ex[q];
                g_logits[idx] = 0.0f;      // restore zero-state
            }
            __shared__ float red[8];
#pragma unroll
            for (int o = 16; o; o >>= 1) lsum += __shfl_xor_sync(0xFFFFFFFFu, lsum, o);
            if ((t & 31) == 0) red[t >> 5] = lsum;
            __syncthreads();
            if (t == 0) {
                float ssum = 0.0f;
#pragma unroll
                for (int k = 0; k < 8; k++) ssum += red[k];
                atomicAdd(&g_sumexp, ssum);
                g_count[bx] = 0;           // restore zero-state
                __threadfence();
                atomicAdd(&g_done, 1);
                while (*(volatile int*)&g_done != 32) __nanosleep(16);
                __threadfence();
                s_inv = 1.0f / __ldcg(&g_sumexp);
                // consumed g_done/g_sumexp: count into g_done2 so the reset
                // block knows when clearing them is safe.
                atomicAdd(&g_done2, 1);
            }
            __syncthreads();
            float inv = s_inv;
#pragma unroll
            for (int q = 0; q < 4; q++)
                out[col + q] = ex[q] * inv;   // final normalized policy
        }

    } else {
        // ---- value head layer 1 (16 blocks) + tail & resets (last arriver) --
        __shared__ float red[256];
        __shared__ int   s_vlast;
        int vb = b - V1_BASE;
        int o = t & 63, chunk = t >> 6;        // 64 outputs x 4 row-sub-chunks
        int row0 = vb * 256 + chunk * 64;

        // prefetch our wv1 slice while edges run
#pragma unroll
        for (int i = 0; i < 64; i += 4)
            asm volatile("prefetch.global.L2 [%0];" ::
                         "l"(&wv1[(size_t)(row0 + i) * 64 + o]));

        if (t == 0) {
            while (*(volatile int*)&g_edge_done != EDGE_BLOCKS) __nanosleep(16);
        }
        __syncthreads();
        __threadfence();

        float acc = 0.0f;
#pragma unroll 8
        for (int i = 0; i < 64; i++)
            acc += g_agg[row0 + i] * wv1[(size_t)(row0 + i) * 64 + o];
        red[t] = acc;
        __syncthreads();
        if (t < 64)
            atomicAdd(&g_v1[t], red[t] + red[t + 64] + red[t + 128] + red[t + 192]);

        __threadfence();
        __syncthreads();
        if (t == 0) {
            int old = atomicAdd(&g_vcount, 1);
            s_vlast = (old == V1_BLOCKS - 1);
        }
        __syncthreads();

        if (s_vlast) {
            // ---- value tail: relu(v1+bv1) -> 32 -> 16 -> 1 (smem staged) ----
            __shared__ float s_w2[64 * 32];
            __shared__ float s_w3[32 * 16];
            __shared__ float s_w4[16];
            __shared__ float v1[64], v2[32], v3[16];
#pragma unroll
            for (int i = 0; i < 8; i++) s_w2[i * 256 + t] = wv2[i * 256 + t];
            s_w3[t]       = wv3[t];
            s_w3[t + 256] = wv3[t + 256];
            if (t < 16) s_w4[t] = wv4[t];
            if (t < 64) {
                v1[t] = fmaxf(__ldcg(&g_v1[t]) + bv1[t], 0.0f);
                g_v1[t] = 0.0f;            // restore zero-state
            }
            __syncthreads();

            if (t < 32) {
                float a = bv2[t];
#pragma unroll 8
                for (int k = 0; k < 64; k++) a += v1[k] * s_w2[k * 32 + t];
                v2[t] = fmaxf(a, 0.0f);
            }
            __syncthreads();
            if (t < 16) {
                float a = bv3[t];
#pragma unroll 8
                for (int k = 0; k < 32; k++) a += v2[k] * s_w3[k * 16 + t];
                v3[t] = fmaxf(a, 0.0f);
            }
            __syncthreads();
            if (t == 0) {
                float a = bv4[0];
#pragma unroll
                for (int k = 0; k < 16; k++) a += v3[k] * s_w4[k];
                out[N_EDGES] = a;          // value scalar after policy[E]
            }

            // ---- state resets, safe once every softmax finisher has passed
            // its g_done spin (g_done2 == 32). Finishers never wait on
            // g_done2, so no circular dependency.
            if (t == 0) {
                while (*(volatile int*)&g_done2 != 32) __nanosleep(16);
            }
            __syncthreads();
#pragma unroll
            for (int i = 0; i < FLATD / 256; i++)
                g_agg[i * 256 + t] = 0.0f; // all readers finished long ago
            if (t == 0) {
                g_done = 0; g_done2 = 0;
                g_prep_done = 0; g_edge_done = 0; g_vcount = 0;
            }
        }
    }
}

extern "C" void kernel_launch(void* const* d_in, const int* in_sizes, int n_in,
                              void* d_out, int out_size) {
    const int*   tgt  = (const int*)  d_in[0];
    const int*   eidx = (const int*)  d_in[1];
    const float* w1   = (const float*)d_in[2];
    const float* b1   = (const float*)d_in[3];
    const float* w2   = (const float*)d_in[4];
    const float* b2   = (const float*)d_in[5];
    const float* wv1  = (const float*)d_in[6];
    const float* bv1  = (const float*)d_in[7];
    const float* wv2  = (const float*)d_in[8];
    const float* bv2  = (const float*)d_in[9];
    const float* wv3  = (const float*)d_in[10];
    const float* bv3  = (const float*)d_in[11];
    const float* wv4  = (const float*)d_in[12];
    const float* bv4  = (const float*)d_in[13];
    const float* wp   = (const float*)d_in[14];
    const float* bp   = (const float*)d_in[15];
    float* out = (float*)d_out;

    mega_kernel<<<TOTAL_BLOCKS, 256>>>(tgt, eidx, w1, b1, w2, b2,
                                       wp, wv1, bp,
                                       bv1, wv2, bv2, wv3, bv3, wv4, bv4,
                                       out);
}

// round 17
// speedup vs baseline: 1.2034x; 1.2034x over previous
#include <cuda_runtime.h>
#include <math_constants.h>

#define N_NODES 1024
#define N_EDGES 32768
#define FLATD   4096   // 4*N

// -------- scratch (device globals; zero-initialized at module load) --------
// Zero-state invariant on entry to each call: g_agg==0, g_logits==0, g_v1==0,
// g_count==0, g_done==0, g_done2==0, g_prep_done==0, g_edge_done==0,
// g_vcount==0. g_sumexp zeroed by prep each call. The last value1 block
// restores everything at the end of the call.
__device__ float  g_agg[FLATD];         // aggregated EdgeConv output [n*4 + c]
__device__ float  g_logits[N_EDGES];    // policy logits (accumulated, no bias)
__device__ float  g_v1[64];             // value layer-1 partials (no bias)
__device__ float  g_sumexp;             // softmax denominator
__device__ int    g_count[32];          // per-column-block completion counters
__device__ int    g_done;               // col-blocks whose sum is published
__device__ int    g_done2;              // col-finishers that consumed g_sumexp
__device__ int    g_prep_done;          // prep blocks completed
__device__ int    g_edge_done;          // edge blocks completed
__device__ int    g_vcount;             // value1 blocks completed
__device__ float  g_tA[N_NODES * 12];   // b1 + [t>=0](w1[t]-w1[N+t]), 12-padded
__device__ float  g_tB[N_NODES * 12];   // [t>=0] w1[N+t], 12-padded

#define PREP_BLOCKS 48
#define EDGE_BLOCKS (N_EDGES / 256)   // 128
#define ROWS_PER_BLK 128              // FLATD / 32 row-slices
#define COLS_PER_BLK 1024             // 256 threads * 4 cols (float4)
#define GEMV_BLOCKS  1024             // 32 col-blocks * 32 row-slices
#define V1_BLOCKS    16
#define GEMV_BASE    (PREP_BLOCKS + EDGE_BLOCKS)          // 176
#define V1_BASE      (GEMV_BASE + GEMV_BLOCKS)            // 1200
#define TOTAL_BLOCKS (V1_BASE + V1_BLOCKS)                // 1216
#define PF_ROWS      24               // L2-prefetched rows per GEMV block

// ===== single mega-kernel: prep | edge | GEMV+softmax | value1+tail+reset ===
__global__ __launch_bounds__(256) void mega_kernel(
        const int* __restrict__ tgt,  const int* __restrict__ eidx,
        const float* __restrict__ w1, const float* __restrict__ b1,
        const float* __restrict__ w2, const float* __restrict__ b2,
        const float* __restrict__ wp, const float* __restrict__ wv1,
        const float* __restrict__ bp,
        const float* __restrict__ bv1,
        const float* __restrict__ wv2, const float* __restrict__ bv2,
        const float* __restrict__ wv3, const float* __restrict__ bv3,
        const float* __restrict__ wv4, const float* __restrict__ bv4,
        float* __restrict__ out) {
    int b = blockIdx.x;
    int t = threadIdx.x;

    if (b < PREP_BLOCKS) {
        // ---- per-node collapsed first-layer rows; one thread per element ----
        int idx = b * 256 + t;               // 12288 threads cover 1024*12
        if (idx == 0) g_sumexp = 0.0f;
        if (idx < N_NODES * 12) {
            int n = idx / 12;
            int k = idx - n * 12;
            float a = 0.0f, bb = 0.0f;
            if (k < 10) {
                int tn = tgt[n];
                a = b1[k];
                if (tn >= 0) {
                    float top = w1[tn * 10 + k];
                    float bot = w1[(N_NODES + tn) * 10 + k];
                    a += top - bot;
                    bb = bot;
                }
            }
            g_tA[idx] = a;
            g_tB[idx] = bb;
        }
        __threadfence();
        __syncthreads();
        if (t == 0) atomicAdd(&g_prep_done, 1);

    } else if (b < GEMV_BASE) {
        // ---- EdgeConv: wait for tables, then 6 float4 loads per edge ----
        int e = (b - PREP_BLOCKS) * 256 + t;
        int s = eidx[e];            // source     (independent of prep)
        int d = eidx[N_EDGES + e];  // dest       (independent of prep)

        if (t == 0) {
            while (*(volatile int*)&g_prep_done != PREP_BLOCKS) __nanosleep(16);
        }
        __syncthreads();
        __threadfence();

        const float4* tA4 = reinterpret_cast<const float4*>(g_tA) + d * 3;
        const float4* tB4 = reinterpret_cast<const float4*>(g_tB) + s * 3;
        float4 a0 = tA4[0], a1 = tA4[1], a2 = tA4[2];
        float4 c0 = tB4[0], c1 = tB4[1], c2 = tB4[2];

        float h[10];
        h[0] = fmaxf(a0.x + c0.x, 0.f);
        h[1] = fmaxf(a0.y + c0.y, 0.f);
        h[2] = fmaxf(a0.z + c0.z, 0.f);
        h[3] = fmaxf(a0.w + c0.w, 0.f);
        h[4] = fmaxf(a1.x + c1.x, 0.f);
        h[5] = fmaxf(a1.y + c1.y, 0.f);
        h[6] = fmaxf(a1.z + c1.z, 0.f);
        h[7] = fmaxf(a1.w + c1.w, 0.f);
        h[8] = fmaxf(a2.x + c2.x, 0.f);
        h[9] = fmaxf(a2.y + c2.y, 0.f);

        float m[4];
#pragma unroll
        for (int c = 0; c < 4; c++) {
            float acc = b2[c];
#pragma unroll
            for (int k = 0; k < 10; k++) acc += h[k] * w2[k * 4 + c];
            m[c] = acc;
        }
        float mx = fmaxf(fmaxf(m[0], m[1]), fmaxf(m[2], m[3]));
        float sum = 0.0f;
#pragma unroll
        for (int c = 0; c < 4; c++) { m[c] = __expf(m[c] - mx); sum += m[c]; }
        float inv = 1.0f / sum;
#pragma unroll
        for (int c = 0; c < 4; c++)
            atomicAdd(&g_agg[d * 4 + c], m[c] * inv);

        __threadfence();
        __syncthreads();
        if (t == 0) atomicAdd(&g_edge_done, 1);

    } else if (b < V1_BASE) {
        // ---- policy GEMV + exp + in-register softmax normalize ----
        __shared__ float sx[ROWS_PER_BLK];
        __shared__ int   s_last;
        __shared__ float s_inv;
        int gb = b - GEMV_BASE;
        int bx = gb & 31;          // col block
        int by = gb >> 5;          // row slice
        int col  = bx * COLS_PER_BLK + t * 4;
        int row0 = by * ROWS_PER_BLK;

        const float4* wptr = reinterpret_cast<const float4*>(
            wp + (size_t)row0 * N_EDGES + col);
        const size_t stride4 = N_EDGES / 4;

        // L2-prefetch the first PF_ROWS rows while the edge phase runs:
        // uses otherwise-idle DRAM bandwidth; zero register cost.
#pragma unroll
        for (int i = 0; i < PF_ROWS; i++)
            asm volatile("prefetch.global.L2 [%0];" ::
                         "l"(wptr + (size_t)i * stride4));

        if (t == 0) {
            while (*(volatile int*)&g_edge_done != EDGE_BLOCKS) __nanosleep(16);
        }
        __syncthreads();
        __threadfence();

        if (t < ROWS_PER_BLK) sx[t] = g_agg[row0 + t];
        __syncthreads();

        float4 acc = make_float4(0.f, 0.f, 0.f, 0.f);
#pragma unroll 8
        for (int i = 0; i < ROWS_PER_BLK; i++) {
            float  xv = sx[i];
            float4 w  = __ldcs(wptr + (size_t)i * stride4);  // streaming
            acc.x += xv * w.x;
            acc.y += xv * w.y;
            acc.z += xv * w.z;
            acc.w += xv * w.w;
        }
        atomicAdd(&g_logits[col + 0], acc.x);
        atomicAdd(&g_logits[col + 1], acc.y);
        atomicAdd(&g_logits[col + 2], acc.z);
        atomicAdd(&g_logits[col + 3], acc.w);

        // publish atomics (fence), all threads fenced (barrier), count in.
        __threadfence();
        __syncthreads();
        if (t == 0) {
            int old = atomicAdd(&g_count[bx], 1);
            s_last = (old == 31);
        }
        __syncthreads();

        if (s_last) {
            // exp epilogue; no max-subtraction (|logit| << 88, exact softmax).
            float ex[4];
            float lsum = 0.0f;
#pragma unroll
            for (int q = 0; q < 4; q++) {
                int idx = col + q;
                float x = __ldcg(&g_logits[idx]) + __ldg(&bp[idx]);
                ex[q] = __expf(x);
                lsum += ex[q];
                g_logits[idx] = 0.0f;      // restore zero-state
            }
            __shared__ float red[8];
#pragma unroll
            for (int o = 16; o; o >>= 1) lsum += __shfl_xor_sync(0xFFFFFFFFu, lsum, o);
            if ((t & 31) == 0) red[t >> 5] = lsum;
            __syncthreads();
            if (t == 0) {
                float ssum = 0.0f;
#pragma unroll
                for (int k = 0; k < 8; k++) ssum += red[k];
                atomicAdd(&g_sumexp, ssum);
                g_count[bx] = 0;           // restore zero-state
                __threadfence();
                atomicAdd(&g_done, 1);
                while (*(volatile int*)&g_done != 32) __nanosleep(16);
                __threadfence();
                s_inv = 1.0f / __ldcg(&g_sumexp);
                // consumed g_done/g_sumexp: count into g_done2 so the reset
                // block knows when clearing them is safe.
                atomicAdd(&g_done2, 1);
            }
            __syncthreads();
            float inv = s_inv;
#pragma unroll
            for (int q = 0; q < 4; q++)
                out[col + q] = ex[q] * inv;   // final normalized policy
        }

    } else {
        // ---- value head layer 1 (16 blocks) + tail & resets (last arriver) --
        __shared__ float red[256];
        __shared__ int   s_vlast;
        int vb = b - V1_BASE;
        int o = t & 63, chunk = t >> 6;        // 64 outputs x 4 row-sub-chunks
        int row0 = vb * 256 + chunk * 64;

        // prefetch our wv1 slice while edges run (64 rows x 64 cols x 4B)
#pragma unroll
        for (int i = 0; i < 64; i += 4)
            asm volatile("prefetch.global.L2 [%0];" ::
                         "l"(&wv1[(size_t)(row0 + i) * 64 + o]));

        if (t == 0) {
            while (*(volatile int*)&g_edge_done != EDGE_BLOCKS) __nanosleep(16);
        }
        __syncthreads();
        __threadfence();

        float acc = 0.0f;
#pragma unroll 8
        for (int i = 0; i < 64; i++)
            acc += g_agg[row0 + i] * wv1[(size_t)(row0 + i) * 64 + o];
        red[t] = acc;
        __syncthreads();
        if (t < 64)
            atomicAdd(&g_v1[t], red[t] + red[t + 64] + red[t + 128] + red[t + 192]);

        __threadfence();
        __syncthreads();
        if (t == 0) {
            int old = atomicAdd(&g_vcount, 1);
            s_vlast = (old == V1_BLOCKS - 1);
        }
        __syncthreads();

        if (s_vlast) {
            // ---- value tail: relu(v1+bv1) -> 32 -> 16 -> 1 (smem staged) ----
            __shared__ float s_w2[64 * 32];
            __shared__ float s_w3[32 * 16];
            __shared__ float s_w4[16];
            __shared__ float v1[64], v2[32], v3[16];
#pragma unroll
            for (int i = 0; i < 8; i++) s_w2[i * 256 + t] = wv2[i * 256 + t];
            s_w3[t]       = wv3[t];
            s_w3[t + 256] = wv3[t + 256];
            if (t < 16) s_w4[t] = wv4[t];
            if (t < 64) {
                v1[t] = fmaxf(__ldcg(&g_v1[t]) + bv1[t], 0.0f);
                g_v1[t] = 0.0f;            // restore zero-state
            }
            __syncthreads();

            if (t < 32) {
                float a = bv2[t];
#pragma unroll 8
                for (int k = 0; k < 64; k++) a += v1[k] * s_w2[k * 32 + t];
                v2[t] = fmaxf(a, 0.0f);
            }
            __syncthreads();
            if (t < 16) {
                float a = bv3[t];
#pragma unroll 8
                for (int k = 0; k < 32; k++) a += v2[k] * s_w3[k * 16 + t];
                v3[t] = fmaxf(a, 0.0f);
            }
            __syncthreads();
            if (t == 0) {
                float a = bv4[0];
#pragma unroll
                for (int k = 0; k < 16; k++) a += v3[k] * s_w4[k];
                out[N_EDGES] = a;          // value scalar after policy[E]
            }

            // ---- state resets, safe once every softmax finisher has passed
            // its g_done spin (g_done2 == 32). Finishers never wait on
            // g_done2, so no circular dependency.
            if (t == 0) {
                while (*(volatile int*)&g_done2 != 32) __nanosleep(16);
            }
            __syncthreads();
#pragma unroll
            for (int i = 0; i < FLATD / 256; i++)
                g_agg[i * 256 + t] = 0.0f; // all readers finished long ago
            if (t == 0) {
                g_done = 0; g_done2 = 0;
                g_prep_done = 0; g_edge_done = 0; g_vcount = 0;
            }
        }
    }
}

extern "C" void kernel_launch(void* const* d_in, const int* in_sizes, int n_in,
                              void* d_out, int out_size) {
    const int*   tgt  = (const int*)  d_in[0];
    const int*   eidx = (const int*)  d_in[1];
    const float* w1   = (const float*)d_in[2];
    const float* b1   = (const float*)d_in[3];
    const float* w2   = (const float*)d_in[4];
    const float* b2   = (const float*)d_in[5];
    const float* wv1  = (const float*)d_in[6];
    const float* bv1  = (const float*)d_in[7];
    const float* wv2  = (const float*)d_in[8];
    const float* bv2  = (const float*)d_in[9];
    const float* wv3  = (const float*)d_in[10];
    const float* bv3  = (const float*)d_in[11];
    const float* wv4  = (const float*)d_in[12];
    const float* bv4  = (const float*)d_in[13];
    const float* wp   = (const float*)d_in[14];
    const float* bp   = (const float*)d_in[15];
    float* out = (float*)d_out;

    mega_kernel<<<TOTAL_BLOCKS, 256>>>(tgt, eidx, w1, b1, w2, b2,
                                       wp, wv1, bp,
                                       bv1, wv2, bv2, wv3, bv3, wv4, bv4,
                                       out);
}